// round 7
// baseline (speedup 1.0000x reference)
#include <cuda_runtime.h>
#include <math.h>

// Problem shape (fixed by the dataset)
#define MAX_NODES  500000
#define MAX_GRAPHS 10000
#define D_FEAT     256
#define CHUNK      256                         // graphs per chunk
#define NCHUNK     ((MAX_GRAPHS + CHUNK - 1) / CHUNK)  // 40
#define GPB        32                          // graphs per passB block

// ---------------- device scratch (no allocations allowed) ----------------
// per-node: (e, e*o0, e*o1, unused) where e = exp(gate_logit)
__device__ float4 g_eo[MAX_NODES];
__device__ int    g_chunk[NCHUNK];             // per-chunk size sums

// ---------------- pass A: one sweep of states (512 MB) --------------------
// 256 threads = 8 warps; each warp handles 4 rows (32 rows/block).
// All 8 float4 loads per thread are issued before any arithmetic -> MLP=8.
// Blocks 0..nchunks-1 ALSO compute one chunk sum of graph_sizes each
// (replaces a standalone chunk kernel). passB reads g_chunk only after
// passA completes (kernel-boundary ordering).
// NOTE on softmax: reference computes exp(g - global_max) / (seg_sum + 1e-16).
// The global max cancels in the ratio; the residual from the +1e-16 term is
// a relative ~2e-14 — far below the 1e-3 tolerance. Gate logits are ~N(0,1)
// (unit-normal states x glorot weights), so exp(g) is safely in fp32 range.
__global__ void __launch_bounds__(256) passA_kernel(
    const float* __restrict__ states,
    const float* __restrict__ gate_w, const float* __restrict__ gate_b,
    const float* __restrict__ out_w,  const float* __restrict__ out_b,
    const int*   __restrict__ sizes,  int n_graphs,
    int n_nodes)
{
    __shared__ __align__(16) float swg[D_FEAT];   // gate_w
    __shared__ __align__(16) float so0[D_FEAT];   // out_w[:,0]
    __shared__ __align__(16) float so1[D_FEAT];   // out_w[:,1]
    __shared__ int s_csum[8];

    const int t = threadIdx.x;
    // stage + deinterleave weights
    swg[t] = gate_w[t];
    float2 ow = ((const float2*)out_w)[t];
    so0[t] = ow.x;
    so1[t] = ow.y;

    // ---- embedded chunk-sum work for the first nchunks blocks ----
    const int nchunks = (n_graphs + CHUNK - 1) / CHUNK;
    if (blockIdx.x < (unsigned)nchunks) {
        const int gi = blockIdx.x * CHUNK + t;
        int v = (gi < n_graphs) ? sizes[gi] : 0;
        #pragma unroll
        for (int off = 16; off; off >>= 1)
            v += __shfl_xor_sync(0xFFFFFFFFu, v, off);
        if ((t & 31) == 0) s_csum[t >> 5] = v;
        __syncthreads();
        if (t == 0) {
            int s = 0;
            #pragma unroll
            for (int w = 0; w < 8; w++) s += s_csum[w];
            g_chunk[blockIdx.x] = s;
        }
    }
    __syncthreads();

    const int warp = t >> 5;
    const int lane = t & 31;

    // hoist this thread's weight slice into registers (reused across 4 rows)
    const float4* wg4 = (const float4*)swg;
    const float4* w04 = (const float4*)so0;
    const float4* w14 = (const float4*)so1;
    const float4 Wg0 = wg4[lane], Wg1 = wg4[lane + 32];
    const float4 W00 = w04[lane], W01 = w04[lane + 32];
    const float4 W10 = w14[lane], W11 = w14[lane + 32];
    const float gb = gate_b[0];
    const float b0 = out_b[0], b1 = out_b[1];

    const long long r0 = ((long long)blockIdx.x * 8 + warp) * 4;
    if (r0 + 3 >= (long long)n_nodes) {
        // ragged tail (not hit for N=500000; kept for generality)
        for (int i = 0; i < 4; i++) {
            long long r = r0 + i;
            if (r >= n_nodes) break;
            const float4* row = (const float4*)(states + r * (long long)D_FEAT);
            float4 v0 = row[lane], v1 = row[lane + 32];
            float ag = v0.x*Wg0.x + v0.y*Wg0.y + v0.z*Wg0.z + v0.w*Wg0.w
                     + v1.x*Wg1.x + v1.y*Wg1.y + v1.z*Wg1.z + v1.w*Wg1.w;
            float a0 = v0.x*W00.x + v0.y*W00.y + v0.z*W00.z + v0.w*W00.w
                     + v1.x*W01.x + v1.y*W01.y + v1.z*W01.z + v1.w*W01.w;
            float a1 = v0.x*W10.x + v0.y*W10.y + v0.z*W10.z + v0.w*W10.w
                     + v1.x*W11.x + v1.y*W11.y + v1.z*W11.z + v1.w*W11.w;
            #pragma unroll
            for (int off = 16; off; off >>= 1) {
                ag += __shfl_xor_sync(0xFFFFFFFFu, ag, off);
                a0 += __shfl_xor_sync(0xFFFFFFFFu, a0, off);
                a1 += __shfl_xor_sync(0xFFFFFFFFu, a1, off);
            }
            if (lane == 0) {
                float e = expf(ag + gb);
                g_eo[r] = make_float4(e, e * (a0 + b0), e * (a1 + b1), 0.f);
            }
        }
        return;
    }

    // fast path: issue all 8 independent LDG.128 up front (MLP=8)
    const float4* base = (const float4*)states;  // 64 float4 per row
    float4 v[8];
    #pragma unroll
    for (int i = 0; i < 4; i++) {
        const float4* row = base + (r0 + i) * 64;
        v[2 * i]     = row[lane];
        v[2 * i + 1] = row[lane + 32];
    }

    float ag[4], a0[4], a1[4];
    #pragma unroll
    for (int i = 0; i < 4; i++) {
        float4 x0 = v[2 * i], x1 = v[2 * i + 1];
        ag[i] = x0.x*Wg0.x + x0.y*Wg0.y + x0.z*Wg0.z + x0.w*Wg0.w
              + x1.x*Wg1.x + x1.y*Wg1.y + x1.z*Wg1.z + x1.w*Wg1.w;
        a0[i] = x0.x*W00.x + x0.y*W00.y + x0.z*W00.z + x0.w*W00.w
              + x1.x*W01.x + x1.y*W01.y + x1.z*W01.z + x1.w*W01.w;
        a1[i] = x0.x*W10.x + x0.y*W10.y + x0.z*W10.z + x0.w*W10.w
              + x1.x*W11.x + x1.y*W11.y + x1.z*W11.z + x1.w*W11.w;
    }

    #pragma unroll
    for (int i = 0; i < 4; i++) {
        #pragma unroll
        for (int off = 16; off; off >>= 1) {
            ag[i] += __shfl_xor_sync(0xFFFFFFFFu, ag[i], off);
            a0[i] += __shfl_xor_sync(0xFFFFFFFFu, a0[i], off);
            a1[i] += __shfl_xor_sync(0xFFFFFFFFu, a1[i], off);
        }
    }

    if (lane == 0) {
        #pragma unroll
        for (int i = 0; i < 4; i++) {
            float e = expf(ag[i] + gb);
            g_eo[r0 + i] = make_float4(e, e * (a0[i] + b0), e * (a1[i] + b1), 0.f);
        }
    }
}

// ---------------- pass B: 32 graphs/block, parallel offset scan ------------
// Base offset for g0 = 32b:
//   sum_{t < c} g_chunk[t] + sum_{t < g0-256c} sizes[256c + t]   (c = g0>>8)
// folded into one 256-thread reduction (<=2 guarded loads/thread).
// Then warp 0 computes the 33-entry local prefix with ONE parallel load
// round + a 5-step shuffle scan (replaces the old thread-0 serial loop of
// 8 dependent L2 loads). Each warp then reduces graphs g0+w, +8, +16, +24.
__global__ void __launch_bounds__(256) passB_kernel(
    const int* __restrict__ sizes, float* __restrict__ out, int n_graphs)
{
    __shared__ int s_part[8];
    __shared__ int s_off[GPB + 1];

    const int t    = threadIdx.x;
    const int warp = t >> 5;
    const int lane = t & 31;
    const int g0   = blockIdx.x * GPB;
    const int c    = g0 >> 8;             // chunk index (<= 39)
    const int w    = g0 & 255;            // graphs within chunk before g0

    int v = 0;
    if (t < c) v += g_chunk[t];           // one guarded load
    if (t < w) v += sizes[(c << 8) + t];  // one guarded load
    #pragma unroll
    for (int off = 16; off; off >>= 1)
        v += __shfl_xor_sync(0xFFFFFFFFu, v, off);
    if (lane == 0) s_part[warp] = v;
    __syncthreads();

    if (warp == 0) {
        // base = sum s_part[0..7]  (all lanes end up with the value)
        int base = (lane < 8) ? s_part[lane] : 0;
        #pragma unroll
        for (int off = 4; off; off >>= 1)
            base += __shfl_xor_sync(0xFFFFFFFFu, base, off);
        base = __shfl_sync(0xFFFFFFFFu, base, 0);
        // parallel load of the 32 local sizes + inclusive shuffle scan
        int gs = (g0 + lane < n_graphs) ? sizes[g0 + lane] : 0;
        int incl = gs;
        #pragma unroll
        for (int off = 1; off < 32; off <<= 1) {
            int nb = __shfl_up_sync(0xFFFFFFFFu, incl, off);
            if (lane >= off) incl += nb;
        }
        s_off[lane] = base + incl - gs;            // exclusive prefix
        if (lane == 31) s_off[GPB] = base + incl;
    }
    __syncthreads();

    #pragma unroll
    for (int k = 0; k < 4; k++) {
        const int idx = warp + k * 8;     // 0..31
        const int g = g0 + idx;
        if (g >= n_graphs) break;
        const int o0 = s_off[idx];
        const int o1 = s_off[idx + 1];

        float se = 0.f, s0 = 0.f, s1 = 0.f;
        for (int i = o0 + lane; i < o1; i += 32) {
            float4 x = g_eo[i];
            se += x.x;
            s0 += x.y;
            s1 += x.z;
        }
        #pragma unroll
        for (int off = 16; off; off >>= 1) {
            se += __shfl_xor_sync(0xFFFFFFFFu, se, off);
            s0 += __shfl_xor_sync(0xFFFFFFFFu, s0, off);
            s1 += __shfl_xor_sync(0xFFFFFFFFu, s1, off);
        }
        if (lane == 0) {
            float inv = 1.0f / (se + 1e-16f);
            ((float2*)out)[g] = make_float2(s0 * inv, s1 * inv);
        }
    }
}

// ---------------- launch ----------------
extern "C" void kernel_launch(void* const* d_in, const int* in_sizes, int n_in,
                              void* d_out, int out_size)
{
    const float* states   = (const float*)d_in[0];
    const int*   graph_sz = (const int*)  d_in[1];
    const float* gate_w   = (const float*)d_in[2];
    const float* gate_b   = (const float*)d_in[3];
    const float* out_w    = (const float*)d_in[4];
    const float* out_b    = (const float*)d_in[5];
    float*       out      = (float*)d_out;

    const int n_nodes  = in_sizes[0] / D_FEAT;   // 500000
    const int n_graphs = in_sizes[1];            // 10000

    const int blocksA = (n_nodes + 31) / 32;     // 15625
    passA_kernel<<<blocksA, 256>>>(states, gate_w, gate_b, out_w, out_b,
                                   graph_sz, n_graphs, n_nodes);

    const int blocksB = (n_graphs + GPB - 1) / GPB;   // 313
    passB_kernel<<<blocksB, 256>>>(graph_sz, out, n_graphs);
}

// round 9
// speedup vs baseline: 1.0118x; 1.0118x over previous
#include <cuda_runtime.h>
#include <math.h>

// Problem shape (fixed by the dataset)
#define MAX_NODES  500000
#define MAX_GRAPHS 10000
#define D_FEAT     256
#define CHUNK      64                          // graphs per chunk
#define NCHUNK     ((MAX_GRAPHS + CHUNK - 1) / CHUNK)  // 157

// ---------------- device scratch (no allocations allowed) ----------------
// per-node: (e, e*o0, e*o1, unused) where e = exp(gate_logit)
__device__ float4 g_eo[MAX_NODES];
__device__ int    g_chunk[NCHUNK];             // per-chunk size sums

// ---------------- pass A: one sweep of states (512 MB) --------------------
// 256 threads = 8 warps; each warp handles 4 rows (32 rows/block).
// All 8 float4 loads per thread are issued before any arithmetic -> MLP=8.
// Blocks 0..nchunks-1 ALSO compute one 64-graph chunk sum of graph_sizes
// (replaces a standalone chunk kernel). passB reads g_chunk only after
// passA completes (kernel-boundary ordering).
// NOTE on softmax: reference computes exp(g - global_max) / (seg_sum + 1e-16).
// The global max cancels in the ratio; the residual from the +1e-16 term is
// a relative ~2e-14 — far below the 1e-3 tolerance. Gate logits are ~N(0,1)
// (unit-normal states x glorot weights), so exp(g) is safely in fp32 range.
__global__ void __launch_bounds__(256) passA_kernel(
    const float* __restrict__ states,
    const float* __restrict__ gate_w, const float* __restrict__ gate_b,
    const float* __restrict__ out_w,  const float* __restrict__ out_b,
    const int*   __restrict__ sizes,  int n_graphs,
    int n_nodes)
{
    __shared__ __align__(16) float swg[D_FEAT];   // gate_w
    __shared__ __align__(16) float so0[D_FEAT];   // out_w[:,0]
    __shared__ __align__(16) float so1[D_FEAT];   // out_w[:,1]
    __shared__ int s_csum[8];

    const int t = threadIdx.x;
    // stage + deinterleave weights
    swg[t] = gate_w[t];
    float2 ow = ((const float2*)out_w)[t];
    so0[t] = ow.x;
    so1[t] = ow.y;

    // ---- embedded 64-graph chunk-sum for the first nchunks blocks ----
    const int nchunks = (n_graphs + CHUNK - 1) / CHUNK;
    if (blockIdx.x < (unsigned)nchunks) {
        const int gi = blockIdx.x * CHUNK + t;      // only t<64 in range
        int v = (t < CHUNK && gi < n_graphs) ? sizes[gi] : 0;
        #pragma unroll
        for (int off = 16; off; off >>= 1)
            v += __shfl_xor_sync(0xFFFFFFFFu, v, off);
        if ((t & 31) == 0) s_csum[t >> 5] = v;
        __syncthreads();
        if (t == 0) {
            int s = 0;
            #pragma unroll
            for (int w = 0; w < 8; w++) s += s_csum[w];
            g_chunk[blockIdx.x] = s;
        }
    }
    __syncthreads();

    const int warp = t >> 5;
    const int lane = t & 31;

    // hoist this thread's weight slice into registers (reused across 4 rows)
    const float4* wg4 = (const float4*)swg;
    const float4* w04 = (const float4*)so0;
    const float4* w14 = (const float4*)so1;
    const float4 Wg0 = wg4[lane], Wg1 = wg4[lane + 32];
    const float4 W00 = w04[lane], W01 = w04[lane + 32];
    const float4 W10 = w14[lane], W11 = w14[lane + 32];
    const float gb = gate_b[0];
    const float b0 = out_b[0], b1 = out_b[1];

    const long long r0 = ((long long)blockIdx.x * 8 + warp) * 4;
    if (r0 + 3 >= (long long)n_nodes) {
        // ragged tail (not hit for N=500000; kept for generality)
        for (int i = 0; i < 4; i++) {
            long long r = r0 + i;
            if (r >= n_nodes) break;
            const float4* row = (const float4*)(states + r * (long long)D_FEAT);
            float4 v0 = row[lane], v1 = row[lane + 32];
            float ag = v0.x*Wg0.x + v0.y*Wg0.y + v0.z*Wg0.z + v0.w*Wg0.w
                     + v1.x*Wg1.x + v1.y*Wg1.y + v1.z*Wg1.z + v1.w*Wg1.w;
            float a0 = v0.x*W00.x + v0.y*W00.y + v0.z*W00.z + v0.w*W00.w
                     + v1.x*W01.x + v1.y*W01.y + v1.z*W01.z + v1.w*W01.w;
            float a1 = v0.x*W10.x + v0.y*W10.y + v0.z*W10.z + v0.w*W10.w
                     + v1.x*W11.x + v1.y*W11.y + v1.z*W11.z + v1.w*W11.w;
            #pragma unroll
            for (int off = 16; off; off >>= 1) {
                ag += __shfl_xor_sync(0xFFFFFFFFu, ag, off);
                a0 += __shfl_xor_sync(0xFFFFFFFFu, a0, off);
                a1 += __shfl_xor_sync(0xFFFFFFFFu, a1, off);
            }
            if (lane == 0) {
                float e = expf(ag + gb);
                g_eo[r] = make_float4(e, e * (a0 + b0), e * (a1 + b1), 0.f);
            }
        }
        return;
    }

    // fast path: issue all 8 independent LDG.128 up front (MLP=8)
    const float4* base = (const float4*)states;  // 64 float4 per row
    float4 v[8];
    #pragma unroll
    for (int i = 0; i < 4; i++) {
        const float4* row = base + (r0 + i) * 64;
        v[2 * i]     = row[lane];
        v[2 * i + 1] = row[lane + 32];
    }

    float ag[4], a0[4], a1[4];
    #pragma unroll
    for (int i = 0; i < 4; i++) {
        float4 x0 = v[2 * i], x1 = v[2 * i + 1];
        ag[i] = x0.x*Wg0.x + x0.y*Wg0.y + x0.z*Wg0.z + x0.w*Wg0.w
              + x1.x*Wg1.x + x1.y*Wg1.y + x1.z*Wg1.z + x1.w*Wg1.w;
        a0[i] = x0.x*W00.x + x0.y*W00.y + x0.z*W00.z + x0.w*W00.w
              + x1.x*W01.x + x1.y*W01.y + x1.z*W01.z + x1.w*W01.w;
        a1[i] = x0.x*W10.x + x0.y*W10.y + x0.z*W10.z + x0.w*W10.w
              + x1.x*W11.x + x1.y*W11.y + x1.z*W11.z + x1.w*W11.w;
    }

    #pragma unroll
    for (int i = 0; i < 4; i++) {
        #pragma unroll
        for (int off = 16; off; off >>= 1) {
            ag[i] += __shfl_xor_sync(0xFFFFFFFFu, ag[i], off);
            a0[i] += __shfl_xor_sync(0xFFFFFFFFu, a0[i], off);
            a1[i] += __shfl_xor_sync(0xFFFFFFFFu, a1[i], off);
        }
    }

    if (lane == 0) {
        #pragma unroll
        for (int i = 0; i < 4; i++) {
            float e = expf(ag[i] + gb);
            g_eo[r0 + i] = make_float4(e, e * (a0[i] + b0), e * (a1[i] + b1), 0.f);
        }
    }
}

// ---------------- pass B: fully independent warp-per-graph -----------------
// No shared memory, no __syncthreads — every warp computes its own graph's
// offset from the two-level hierarchy (g_chunk + in-chunk sizes) with
// lane-parallel guarded loads, then reduces that graph's g_eo range.
// Max concurrency: 10000 independent warps hide all L2 latency.
__global__ void __launch_bounds__(256) passB_kernel(
    const int* __restrict__ sizes, float* __restrict__ out, int n_graphs)
{
    const int warp = threadIdx.x >> 5;
    const int lane = threadIdx.x & 31;
    const int g    = blockIdx.x * 8 + warp;
    if (g >= n_graphs) return;

    const int c = g >> 6;           // chunk index (<= 156)
    const int w = g & 63;           // graphs within chunk before g (<= 63)

    // o0 = sum_{t<c} g_chunk[t] + sum_{t<w} sizes[64c+t]
    int v = 0;
    for (int i = lane; i < c; i += 32) v += g_chunk[i];          // <=5 rounds
    for (int i = lane; i < w; i += 32) v += sizes[(c << 6) + i]; // <=2 rounds
    #pragma unroll
    for (int off = 16; off; off >>= 1)
        v += __shfl_xor_sync(0xFFFFFFFFu, v, off);
    const int o0 = v;
    const int o1 = o0 + sizes[g];   // broadcast load, L2-hot

    float se = 0.f, s0 = 0.f, s1 = 0.f;
    for (int i = o0 + lane; i < o1; i += 32) {
        float4 x = g_eo[i];
        se += x.x;
        s0 += x.y;
        s1 += x.z;
    }
    #pragma unroll
    for (int off = 16; off; off >>= 1) {
        se += __shfl_xor_sync(0xFFFFFFFFu, se, off);
        s0 += __shfl_xor_sync(0xFFFFFFFFu, s0, off);
        s1 += __shfl_xor_sync(0xFFFFFFFFu, s1, off);
    }
    if (lane == 0) {
        float inv = 1.0f / (se + 1e-16f);
        ((float2*)out)[g] = make_float2(s0 * inv, s1 * inv);
    }
}

// ---------------- launch ----------------
extern "C" void kernel_launch(void* const* d_in, const int* in_sizes, int n_in,
                              void* d_out, int out_size)
{
    const float* states   = (const float*)d_in[0];
    const int*   graph_sz = (const int*)  d_in[1];
    const float* gate_w   = (const float*)d_in[2];
    const float* gate_b   = (const float*)d_in[3];
    const float* out_w    = (const float*)d_in[4];
    const float* out_b    = (const float*)d_in[5];
    float*       out      = (float*)d_out;

    const int n_nodes  = in_sizes[0] / D_FEAT;   // 500000
    const int n_graphs = in_sizes[1];            // 10000

    const int blocksA = (n_nodes + 31) / 32;     // 15625
    passA_kernel<<<blocksA, 256>>>(states, gate_w, gate_b, out_w, out_b,
                                   graph_sz, n_graphs, n_nodes);

    const int blocksB = (n_graphs + 7) / 8;      // 1250
    passB_kernel<<<blocksB, 256>>>(graph_sz, out, n_graphs);
}

// round 10
// speedup vs baseline: 1.0242x; 1.0123x over previous
#include <cuda_runtime.h>
#include <math.h>

// Problem shape (fixed by the dataset)
#define MAX_NODES  500000
#define MAX_GRAPHS 10000
#define D_FEAT     256
#define CHUNK      64                                   // graphs per chunk
#define NCHUNK     ((MAX_GRAPHS + CHUNK - 1) / CHUNK)   // 157
#define SUPER      1024                                 // graphs per superchunk (=16 chunks)
#define NSUPER     ((MAX_GRAPHS + SUPER - 1) / SUPER)   // 10

// ---------------- device scratch (no allocations allowed) ----------------
// per-node: (e, e*o0, e*o1, unused) where e = exp(gate_logit)
__device__ float4 g_eo[MAX_NODES];
__device__ int    g_chunk[NCHUNK];   // 64-graph size sums
__device__ int    g_super[NSUPER];   // 1024-graph size sums

// ---------------- pass A: one sweep of states (512 MB) --------------------
// 256 threads = 8 warps; each warp handles 4 rows (32 rows/block).
// All 8 float4 loads per thread are issued before any arithmetic -> MLP=8.
// Blocks 0..nchunks-1 also compute one 64-graph chunk sum; blocks
// nchunks..nchunks+nsuper-1 compute one 1024-graph super sum. passB reads
// them only after passA completes (kernel-boundary ordering).
// NOTE on softmax: reference computes exp(g - global_max) / (seg_sum + 1e-16).
// The global max cancels in the ratio; the residual from the +1e-16 term is
// a relative ~2e-14 — far below the 1e-3 tolerance. Gate logits are ~N(0,1)
// (unit-normal states x glorot weights), so exp(g) is safely in fp32 range.
__global__ void __launch_bounds__(256) passA_kernel(
    const float* __restrict__ states,
    const float* __restrict__ gate_w, const float* __restrict__ gate_b,
    const float* __restrict__ out_w,  const float* __restrict__ out_b,
    const int*   __restrict__ sizes,  int n_graphs,
    int n_nodes)
{
    __shared__ __align__(16) float swg[D_FEAT];   // gate_w
    __shared__ __align__(16) float so0[D_FEAT];   // out_w[:,0]
    __shared__ __align__(16) float so1[D_FEAT];   // out_w[:,1]
    __shared__ int s_csum[8];

    const int t = threadIdx.x;
    // stage + deinterleave weights
    swg[t] = gate_w[t];
    float2 ow = ((const float2*)out_w)[t];
    so0[t] = ow.x;
    so1[t] = ow.y;

    // ---- embedded size-sum work for the first nchunks+nsuper blocks ----
    const int nchunks = (n_graphs + CHUNK - 1) / CHUNK;
    const int nsuper  = (n_graphs + SUPER - 1) / SUPER;
    if (blockIdx.x < (unsigned)(nchunks + nsuper)) {
        int v = 0;
        if (blockIdx.x < (unsigned)nchunks) {
            const int gi = blockIdx.x * CHUNK + t;      // only t<64 in range
            v = (t < CHUNK && gi < n_graphs) ? sizes[gi] : 0;
        } else {
            const int s = blockIdx.x - nchunks;
            const int base = s * SUPER;
            #pragma unroll
            for (int k = 0; k < SUPER / 256; k++) {     // 4 loads
                int gi = base + t + (k << 8);
                if (gi < n_graphs && gi < base + SUPER) v += sizes[gi];
            }
        }
        #pragma unroll
        for (int off = 16; off; off >>= 1)
            v += __shfl_xor_sync(0xFFFFFFFFu, v, off);
        if ((t & 31) == 0) s_csum[t >> 5] = v;
        __syncthreads();
        if (t == 0) {
            int s = 0;
            #pragma unroll
            for (int w = 0; w < 8; w++) s += s_csum[w];
            if (blockIdx.x < (unsigned)nchunks) g_chunk[blockIdx.x] = s;
            else                                g_super[blockIdx.x - nchunks] = s;
        }
    }
    __syncthreads();

    const int warp = t >> 5;
    const int lane = t & 31;

    // hoist this thread's weight slice into registers (reused across 4 rows)
    const float4* wg4 = (const float4*)swg;
    const float4* w04 = (const float4*)so0;
    const float4* w14 = (const float4*)so1;
    const float4 Wg0 = wg4[lane], Wg1 = wg4[lane + 32];
    const float4 W00 = w04[lane], W01 = w04[lane + 32];
    const float4 W10 = w14[lane], W11 = w14[lane + 32];
    const float gb = gate_b[0];
    const float b0 = out_b[0], b1 = out_b[1];

    const long long r0 = ((long long)blockIdx.x * 8 + warp) * 4;
    if (r0 + 3 >= (long long)n_nodes) {
        // ragged tail (not hit for N=500000; kept for generality)
        for (int i = 0; i < 4; i++) {
            long long r = r0 + i;
            if (r >= n_nodes) break;
            const float4* row = (const float4*)(states + r * (long long)D_FEAT);
            float4 v0 = row[lane], v1 = row[lane + 32];
            float ag = v0.x*Wg0.x + v0.y*Wg0.y + v0.z*Wg0.z + v0.w*Wg0.w
                     + v1.x*Wg1.x + v1.y*Wg1.y + v1.z*Wg1.z + v1.w*Wg1.w;
            float a0 = v0.x*W00.x + v0.y*W00.y + v0.z*W00.z + v0.w*W00.w
                     + v1.x*W01.x + v1.y*W01.y + v1.z*W01.z + v1.w*W01.w;
            float a1 = v0.x*W10.x + v0.y*W10.y + v0.z*W10.z + v0.w*W10.w
                     + v1.x*W11.x + v1.y*W11.y + v1.z*W11.z + v1.w*W11.w;
            #pragma unroll
            for (int off = 16; off; off >>= 1) {
                ag += __shfl_xor_sync(0xFFFFFFFFu, ag, off);
                a0 += __shfl_xor_sync(0xFFFFFFFFu, a0, off);
                a1 += __shfl_xor_sync(0xFFFFFFFFu, a1, off);
            }
            if (lane == 0) {
                float e = expf(ag + gb);
                g_eo[r] = make_float4(e, e * (a0 + b0), e * (a1 + b1), 0.f);
            }
        }
        return;
    }

    // fast path: issue all 8 independent LDG.128 up front (MLP=8)
    const float4* base = (const float4*)states;  // 64 float4 per row
    float4 v[8];
    #pragma unroll
    for (int i = 0; i < 4; i++) {
        const float4* row = base + (r0 + i) * 64;
        v[2 * i]     = row[lane];
        v[2 * i + 1] = row[lane + 32];
    }

    float ag[4], a0[4], a1[4];
    #pragma unroll
    for (int i = 0; i < 4; i++) {
        float4 x0 = v[2 * i], x1 = v[2 * i + 1];
        ag[i] = x0.x*Wg0.x + x0.y*Wg0.y + x0.z*Wg0.z + x0.w*Wg0.w
              + x1.x*Wg1.x + x1.y*Wg1.y + x1.z*Wg1.z + x1.w*Wg1.w;
        a0[i] = x0.x*W00.x + x0.y*W00.y + x0.z*W00.z + x0.w*W00.w
              + x1.x*W01.x + x1.y*W01.y + x1.z*W01.z + x1.w*W01.w;
        a1[i] = x0.x*W10.x + x0.y*W10.y + x0.z*W10.z + x0.w*W10.w
              + x1.x*W11.x + x1.y*W11.y + x1.z*W11.z + x1.w*W11.w;
    }

    #pragma unroll
    for (int i = 0; i < 4; i++) {
        #pragma unroll
        for (int off = 16; off; off >>= 1) {
            ag[i] += __shfl_xor_sync(0xFFFFFFFFu, ag[i], off);
            a0[i] += __shfl_xor_sync(0xFFFFFFFFu, a0[i], off);
            a1[i] += __shfl_xor_sync(0xFFFFFFFFu, a1[i], off);
        }
    }

    if (lane == 0) {
        #pragma unroll
        for (int i = 0; i < 4; i++) {
            float e = expf(ag[i] + gb);
            g_eo[r0 + i] = make_float4(e, e * (a0[i] + b0), e * (a1[i] + b1), 0.f);
        }
    }
}

// ---------------- pass B: warp-per-graph, ONE offset load round ------------
// Offset for graph g via 3 levels, ALL loads issued concurrently:
//   lane<s:        g_super[lane]              (s = g>>10, <= 9)
//   lane<c&15:     g_chunk[16s + lane]        (c = g>>6, <= 15 chunks in super)
//   i<=w (2 ld):   sizes[64c + i]             (w = g&63; INCLUSIVE through g)
// One shuffle reduce gives o1 (inclusive); sizes[g] is shuffled out of the
// owning lane -> o0 = o1 - sizes[g]. Then the main reduction prefetches 4
// guarded float4s (segments avg 50, max ~80 << 128) -> one DRAM round.
__global__ void __launch_bounds__(256) passB_kernel(
    const int* __restrict__ sizes, float* __restrict__ out, int n_graphs)
{
    const int warp = threadIdx.x >> 5;
    const int lane = threadIdx.x & 31;
    const int g    = blockIdx.x * 8 + warp;
    if (g >= n_graphs) return;

    const int s  = g >> 10;          // super index
    const int c  = g >> 6;           // global chunk index
    const int cb = c & 15;           // chunks before c within its super
    const int w  = g & 63;           // in-chunk position (inclusive target)

    // one parallel round: all four loads independent
    int v = 0;
    if (lane < s)  v += g_super[lane];
    if (lane < cb) v += g_chunk[(s << 4) + lane];
    const int cbase = c << 6;
    int sA = (lane      <= w) ? sizes[cbase + lane]      : 0;  // idx <= g < n_graphs
    int sB = (lane + 32 <= w) ? sizes[cbase + lane + 32] : 0;
    v += sA + sB;
    // extract sizes[g] from its owning lane before reducing
    int szsel = (w < 32) ? sA : sB;
    const int sz = __shfl_sync(0xFFFFFFFFu, szsel, w & 31);
    #pragma unroll
    for (int off = 16; off; off >>= 1)
        v += __shfl_xor_sync(0xFFFFFFFFu, v, off);
    const int o1 = v;          // inclusive prefix through g
    const int o0 = o1 - sz;

    // main reduction: prefetch 4 guarded float4 loads (one round)
    const float4 z = make_float4(0.f, 0.f, 0.f, 0.f);
    const int i = o0 + lane;
    float4 x0 = (i      < o1) ? g_eo[i]      : z;
    float4 x1 = (i + 32 < o1) ? g_eo[i + 32] : z;
    float4 x2 = (i + 64 < o1) ? g_eo[i + 64] : z;
    float4 x3 = (i + 96 < o1) ? g_eo[i + 96] : z;
    float se = x0.x + x1.x + x2.x + x3.x;
    float s0 = x0.y + x1.y + x2.y + x3.y;
    float s1 = x0.z + x1.z + x2.z + x3.z;
    for (int j = i + 128; j < o1; j += 32) {   // essentially never taken
        float4 x = g_eo[j];
        se += x.x; s0 += x.y; s1 += x.z;
    }
    #pragma unroll
    for (int off = 16; off; off >>= 1) {
        se += __shfl_xor_sync(0xFFFFFFFFu, se, off);
        s0 += __shfl_xor_sync(0xFFFFFFFFu, s0, off);
        s1 += __shfl_xor_sync(0xFFFFFFFFu, s1, off);
    }
    if (lane == 0) {
        float inv = 1.0f / (se + 1e-16f);
        ((float2*)out)[g] = make_float2(s0 * inv, s1 * inv);
    }
}

// ---------------- launch ----------------
extern "C" void kernel_launch(void* const* d_in, const int* in_sizes, int n_in,
                              void* d_out, int out_size)
{
    const float* states   = (const float*)d_in[0];
    const int*   graph_sz = (const int*)  d_in[1];
    const float* gate_w   = (const float*)d_in[2];
    const float* gate_b   = (const float*)d_in[3];
    const float* out_w    = (const float*)d_in[4];
    const float* out_b    = (const float*)d_in[5];
    float*       out      = (float*)d_out;

    const int n_nodes  = in_sizes[0] / D_FEAT;   // 500000
    const int n_graphs = in_sizes[1];            // 10000

    const int blocksA = (n_nodes + 31) / 32;     // 15625
    passA_kernel<<<blocksA, 256>>>(states, gate_w, gate_b, out_w, out_b,
                                   graph_sz, n_graphs, n_nodes);

    const int blocksB = (n_graphs + 7) / 8;      // 1250
    passB_kernel<<<blocksB, 256>>>(graph_sz, out, n_graphs);
}